// round 3
// baseline (speedup 1.0000x reference)
#include <cuda_runtime.h>
#include <math_constants.h>

#define BB 64
#define DD 256
#define OO 1024
#define KK 1024

#define BLOCK_O 128
#define BLOCK_K 64
#define NT 256

// Scratch for ||e_k||^2 (allocation-free: __device__ global).
__device__ float g_e2[KK];

// ---------------------------------------------------------------------------
// Kernel 1: e2[k] = sum_d emb[d,k]^2.  Threads over k -> fully coalesced.
// ---------------------------------------------------------------------------
__global__ void e2_kernel(const float* __restrict__ emb) {
    int k = blockIdx.x * blockDim.x + threadIdx.x;
    float s = 0.f;
#pragma unroll 8
    for (int d = 0; d < DD; ++d) {
        float v = emb[d * KK + k];
        s = fmaf(v, v, s);
    }
    g_e2[k] = s;
}

// ---------------------------------------------------------------------------
// Kernel 2: fused GEMM + running argmin + gather.
// Block: one b, 128 o's. x-tile (256x128 f32) resident in smem,
// emb streamed in 256x64 tiles. Thread micro-tile: 8 o x 4 k.
// ---------------------------------------------------------------------------
extern __shared__ float smem[];

__global__ __launch_bounds__(NT, 1)
void vq_kernel(const float* __restrict__ x, const float* __restrict__ emb,
               float* __restrict__ quant, float* __restrict__ argout) {
    float* xs = smem;                    // [DD][BLOCK_O]  128 KB
    float* es = smem + DD * BLOCK_O;     // [DD][BLOCK_K]   64 KB
    __shared__ int ks[BLOCK_O];

    const int b  = blockIdx.y;
    const int o0 = blockIdx.x * BLOCK_O;
    const int tid = threadIdx.x;
    const int tx = tid & 15;   // k-group: 4 consecutive k
    const int ty = tid >> 4;   // o-group: 8 consecutive o

    // Load x tile: x[b, d, o0+o] -> xs[d*128 + o]. Consecutive tid = consecutive o
    // -> 512B coalesced rows.
    const float* xb = x + (size_t)b * DD * OO + o0;
    for (int idx = tid; idx < DD * BLOCK_O; idx += NT) {
        int d = idx >> 7;
        int o = idx & (BLOCK_O - 1);
        xs[idx] = xb[d * OO + o];
    }

    float bestv[8];
    int   bestk[8];
#pragma unroll
    for (int i = 0; i < 8; ++i) { bestv[i] = CUDART_INF_F; bestk[i] = 0; }

    for (int kt = 0; kt < KK; kt += BLOCK_K) {
        __syncthreads();   // prior compute done (and initial x load) before es overwrite
        for (int idx = tid; idx < DD * BLOCK_K; idx += NT) {
            int d = idx >> 6;
            int k = idx & (BLOCK_K - 1);
            es[idx] = emb[d * KK + kt + k];
        }
        __syncthreads();

        float acc[8][4];
#pragma unroll
        for (int i = 0; i < 8; ++i)
#pragma unroll
            for (int j = 0; j < 4; ++j) acc[i][j] = 0.f;

#pragma unroll 8
        for (int d = 0; d < DD; ++d) {
            const float4 a0 = reinterpret_cast<const float4*>(xs + d * BLOCK_O + ty * 8)[0];
            const float4 a1 = reinterpret_cast<const float4*>(xs + d * BLOCK_O + ty * 8)[1];
            const float4 bv = reinterpret_cast<const float4*>(es + d * BLOCK_K + tx * 4)[0];
            const float a[8] = {a0.x, a0.y, a0.z, a0.w, a1.x, a1.y, a1.z, a1.w};
            const float bq[4] = {bv.x, bv.y, bv.z, bv.w};
#pragma unroll
            for (int i = 0; i < 8; ++i)
#pragma unroll
                for (int j = 0; j < 4; ++j)
                    acc[i][j] = fmaf(a[i], bq[j], acc[i][j]);
        }

        // Running argmin update. Per-thread k strictly ascending across (kt, j)
        // so strict '<' keeps the first (lowest) index on ties, matching argmin.
#pragma unroll
        for (int j = 0; j < 4; ++j) {
            const int k = kt + tx * 4 + j;
            const float e2 = g_e2[k];
#pragma unroll
            for (int i = 0; i < 8; ++i) {
                float val = fmaf(-2.f, acc[i][j], e2);
                if (val < bestv[i]) { bestv[i] = val; bestk[i] = k; }
            }
        }
    }

    // Reduce across the 16 k-lanes (tx) sharing the same o rows.
    // tid = ty*16 + tx -> xor offsets <= 8 stay inside the 16-lane group.
#pragma unroll
    for (int i = 0; i < 8; ++i) {
        float v = bestv[i];
        int   kk = bestk[i];
#pragma unroll
        for (int off = 8; off >= 1; off >>= 1) {
            float ov = __shfl_xor_sync(0xFFFFFFFFu, v,  off);
            int   ok = __shfl_xor_sync(0xFFFFFFFFu, kk, off);
            if (ov < v || (ov == v && ok < kk)) { v = ov; kk = ok; }
        }
        if (tx == 0) {
            const int o = ty * 8 + i;
            ks[o] = kk;
            if (argout) argout[b * OO + o0 + o] = (float)kk;
        }
    }
    __syncthreads();

    // Gather quant[b,d,o] = emb[d, ks[o]]. Stores coalesced over o; loads hit
    // the L2-resident 1 MB codebook.
    if (quant) {
        float* qb = quant + (size_t)b * DD * OO + o0;
        for (int idx = tid; idx < DD * BLOCK_O; idx += NT) {
            int d = idx >> 7;
            int o = idx & (BLOCK_O - 1);
            qb[d * OO + o] = emb[d * KK + ks[o]];
        }
    }
}

// ---------------------------------------------------------------------------
extern "C" void kernel_launch(void* const* d_in, const int* in_sizes, int n_in,
                              void* d_out, int out_size) {
    const float* x   = (const float*)d_in[0];
    const float* emb = (const float*)d_in[1];
    float* out = (float*)d_out;

    const int QN = BB * DD * OO;   // quant elements
    const int AN = BB * OO;        // argmin elements

    float* quant  = nullptr;
    float* argout = nullptr;
    if (out_size >= QN) {
        quant = out;
        if (out_size >= QN + AN) argout = out + QN;
    } else if (out_size >= AN) {
        argout = out;   // argmin-only layout
    }

    const int smem_bytes = (DD * BLOCK_O + DD * BLOCK_K) * (int)sizeof(float); // 192 KB
    cudaFuncSetAttribute(vq_kernel, cudaFuncAttributeMaxDynamicSharedMemorySize, smem_bytes);

    e2_kernel<<<KK / 256, 256>>>(emb);

    dim3 grid(OO / BLOCK_O, BB);
    vq_kernel<<<grid, NT, smem_bytes>>>(x, emb, quant, argout);
}

// round 4
// speedup vs baseline: 1.0023x; 1.0023x over previous
#include <cuda_runtime.h>
#include <math_constants.h>

#define BB 64
#define DD 256
#define OO 1024
#define KK 1024

#define BLOCK_O 128
#define BLOCK_K 64
#define NT 256

// Scratch for ||e_k||^2 (allocation-free: __device__ global).
__device__ float g_e2[KK];

// ---------------------------------------------------------------------------
// Kernel 1: e2[k] = sum_d emb[d,k]^2.  Threads over k -> fully coalesced.
// ---------------------------------------------------------------------------
__global__ void e2_kernel(const float* __restrict__ emb) {
    int k = blockIdx.x * blockDim.x + threadIdx.x;
    float s = 0.f;
#pragma unroll 8
    for (int d = 0; d < DD; ++d) {
        float v = emb[d * KK + k];
        s = fmaf(v, v, s);
    }
    g_e2[k] = s;
}

// ---------------------------------------------------------------------------
// Kernel 2: fused GEMM + running argmin + gather.
// Block: one b, 128 o's. x-tile (256x128 f32) resident in smem,
// emb streamed in 256x64 tiles. Thread micro-tile: 8 o x 4 k.
// ---------------------------------------------------------------------------
extern __shared__ float smem[];

__global__ __launch_bounds__(NT, 1)
void vq_kernel(const float* __restrict__ x, const float* __restrict__ emb,
               float* __restrict__ quant, float* __restrict__ argout) {
    float* xs = smem;                    // [DD][BLOCK_O]  128 KB
    float* es = smem + DD * BLOCK_O;     // [DD][BLOCK_K]   64 KB
    __shared__ int ks[BLOCK_O];

    const int b  = blockIdx.y;
    const int o0 = blockIdx.x * BLOCK_O;
    const int tid = threadIdx.x;
    const int tx = tid & 15;   // k-group: 4 consecutive k
    const int ty = tid >> 4;   // o-group: 8 consecutive o

    // Load x tile: x[b, d, o0+o] -> xs[d*128 + o]. Consecutive tid = consecutive o
    // -> 512B coalesced rows.
    const float* xb = x + (size_t)b * DD * OO + o0;
    for (int idx = tid; idx < DD * BLOCK_O; idx += NT) {
        int d = idx >> 7;
        int o = idx & (BLOCK_O - 1);
        xs[idx] = xb[d * OO + o];
    }

    float bestv[8];
    int   bestk[8];
#pragma unroll
    for (int i = 0; i < 8; ++i) { bestv[i] = CUDART_INF_F; bestk[i] = 0; }

    for (int kt = 0; kt < KK; kt += BLOCK_K) {
        __syncthreads();   // prior compute done (and initial x load) before es overwrite
        for (int idx = tid; idx < DD * BLOCK_K; idx += NT) {
            int d = idx >> 6;
            int k = idx & (BLOCK_K - 1);
            es[idx] = emb[d * KK + kt + k];
        }
        __syncthreads();

        float acc[8][4];
#pragma unroll
        for (int i = 0; i < 8; ++i)
#pragma unroll
            for (int j = 0; j < 4; ++j) acc[i][j] = 0.f;

#pragma unroll 8
        for (int d = 0; d < DD; ++d) {
            const float4 a0 = reinterpret_cast<const float4*>(xs + d * BLOCK_O + ty * 8)[0];
            const float4 a1 = reinterpret_cast<const float4*>(xs + d * BLOCK_O + ty * 8)[1];
            const float4 bv = reinterpret_cast<const float4*>(es + d * BLOCK_K + tx * 4)[0];
            const float a[8] = {a0.x, a0.y, a0.z, a0.w, a1.x, a1.y, a1.z, a1.w};
            const float bq[4] = {bv.x, bv.y, bv.z, bv.w};
#pragma unroll
            for (int i = 0; i < 8; ++i)
#pragma unroll
                for (int j = 0; j < 4; ++j)
                    acc[i][j] = fmaf(a[i], bq[j], acc[i][j]);
        }

        // Running argmin update. Per-thread k strictly ascending across (kt, j)
        // so strict '<' keeps the first (lowest) index on ties, matching argmin.
#pragma unroll
        for (int j = 0; j < 4; ++j) {
            const int k = kt + tx * 4 + j;
            const float e2 = g_e2[k];
#pragma unroll
            for (int i = 0; i < 8; ++i) {
                float val = fmaf(-2.f, acc[i][j], e2);
                if (val < bestv[i]) { bestv[i] = val; bestk[i] = k; }
            }
        }
    }

    // Reduce across the 16 k-lanes (tx) sharing the same o rows.
    // tid = ty*16 + tx -> xor offsets <= 8 stay inside the 16-lane group.
#pragma unroll
    for (int i = 0; i < 8; ++i) {
        float v = bestv[i];
        int   kk = bestk[i];
#pragma unroll
        for (int off = 8; off >= 1; off >>= 1) {
            float ov = __shfl_xor_sync(0xFFFFFFFFu, v,  off);
            int   ok = __shfl_xor_sync(0xFFFFFFFFu, kk, off);
            if (ov < v || (ov == v && ok < kk)) { v = ov; kk = ok; }
        }
        if (tx == 0) {
            const int o = ty * 8 + i;
            ks[o] = kk;
            if (argout) argout[b * OO + o0 + o] = (float)kk;
        }
    }
    __syncthreads();

    // Gather quant[b,d,o] = emb[d, ks[o]]. Stores coalesced over o; loads hit
    // the L2-resident 1 MB codebook.
    if (quant) {
        float* qb = quant + (size_t)b * DD * OO + o0;
        for (int idx = tid; idx < DD * BLOCK_O; idx += NT) {
            int d = idx >> 7;
            int o = idx & (BLOCK_O - 1);
            qb[d * OO + o] = emb[d * KK + ks[o]];
        }
    }
}

// ---------------------------------------------------------------------------
extern "C" void kernel_launch(void* const* d_in, const int* in_sizes, int n_in,
                              void* d_out, int out_size) {
    const float* x   = (const float*)d_in[0];
    const float* emb = (const float*)d_in[1];
    float* out = (float*)d_out;

    const int QN = BB * DD * OO;   // quant elements
    const int AN = BB * OO;        // argmin elements

    float* quant  = nullptr;
    float* argout = nullptr;
    if (out_size >= QN) {
        quant = out;
        if (out_size >= QN + AN) argout = out + QN;
    } else if (out_size >= AN) {
        argout = out;   // argmin-only layout
    }

    const int smem_bytes = (DD * BLOCK_O + DD * BLOCK_K) * (int)sizeof(float); // 192 KB
    cudaFuncSetAttribute(vq_kernel, cudaFuncAttributeMaxDynamicSharedMemorySize, smem_bytes);

    e2_kernel<<<KK / 256, 256>>>(emb);

    dim3 grid(OO / BLOCK_O, BB);
    vq_kernel<<<grid, NT, smem_bytes>>>(x, emb, quant, argout);
}

// round 6
// speedup vs baseline: 1.4285x; 1.4253x over previous
#include <cuda_runtime.h>
#include <math_constants.h>
#include <cstdint>

#define BB 64
#define DD 256
#define OO 1024
#define KK 1024

#define BLOCK_O 128
#define BLOCK_K 64
#define NT 256

// Scratch for ||e_k||^2 (allocation-free: __device__ global).
__device__ float g_e2[KK];

// Packed fp32x2 FMA (Blackwell FFMA2): two bitwise-exact fp32 FMAs / instr.
#define FMA2(c, a, b) \
    asm("fma.rn.f32x2 %0, %1, %2, %0;" : "+l"(c) : "l"(a), "l"(b))
#define PACK2(d, f) \
    asm("mov.b64 %0, {%1, %1};" : "=l"(d) : "f"(f))

// ---------------------------------------------------------------------------
// Kernel 1: e2[k] = sum_d emb[d,k]^2.
// ---------------------------------------------------------------------------
__global__ void e2_kernel(const float* __restrict__ emb) {
    int k = blockIdx.x * blockDim.x + threadIdx.x;
    float s = 0.f;
#pragma unroll 8
    for (int d = 0; d < DD; ++d) {
        float v = emb[d * KK + k];
        s = fmaf(v, v, s);
    }
    g_e2[k] = s;
}

// ---------------------------------------------------------------------------
// Kernel 2: fused GEMM (FFMA2) + running argmin + gather.
// Block: one b, 128 o's. x-tile (256x128 f32) resident in smem,
// emb streamed in 256x64 tiles. Thread micro-tile: 8 o x 4 k,
// accumulated as 4 o-pairs x 4 k in packed f32x2 registers.
// ---------------------------------------------------------------------------
extern __shared__ float smem[];

__global__ __launch_bounds__(NT, 1)
void vq_kernel(const float* __restrict__ x, const float* __restrict__ emb,
               float* __restrict__ quant, float* __restrict__ argout) {
    float* xs = smem;                    // [DD][BLOCK_O]  128 KB
    float* es = smem + DD * BLOCK_O;     // [DD][BLOCK_K]   64 KB
    __shared__ int ks[BLOCK_O];

    const int b  = blockIdx.y;
    const int o0 = blockIdx.x * BLOCK_O;
    const int tid = threadIdx.x;
    const int tx = tid & 15;   // k-group: 4 consecutive k
    const int ty = tid >> 4;   // o-group: 8 consecutive o

    // Load x tile (float4-vectorized): x[b, d, o0+o] -> xs[d*128 + o].
    {
        const float4* xb4 = reinterpret_cast<const float4*>(x + (size_t)b * DD * OO + o0);
        float4* xs4 = reinterpret_cast<float4*>(xs);
#pragma unroll
        for (int i = 0; i < (DD * BLOCK_O / 4) / NT; ++i) {
            int idx4 = tid + i * NT;               // over 8192 float4
            int d = idx4 >> 5;                     // 32 float4 per row of 128
            int o4 = idx4 & 31;
            xs4[idx4] = xb4[d * (OO / 4) + o4];
        }
    }

    float bestv[8];
    int   bestk[8];
#pragma unroll
    for (int i = 0; i < 8; ++i) { bestv[i] = CUDART_INF_F; bestk[i] = 0; }

    for (int kt = 0; kt < KK; kt += BLOCK_K) {
        __syncthreads();   // prior compute (and initial x load) done before es overwrite
        {
            const float4* eb4 = reinterpret_cast<const float4*>(emb + kt);
            float4* es4 = reinterpret_cast<float4*>(es);
#pragma unroll
            for (int i = 0; i < (DD * BLOCK_K / 4) / NT; ++i) {
                int idx4 = tid + i * NT;           // over 4096 float4
                int d = idx4 >> 4;                 // 16 float4 per row of 64
                int k4 = idx4 & 15;
                es4[idx4] = eb4[d * (KK / 4) + k4];
            }
        }
        __syncthreads();

        // acc2[i2][j]: packed pair of o = (ty*8 + 2*i2, +1) against k = tx*4 + j
        uint64_t acc2[4][4];
#pragma unroll
        for (int i2 = 0; i2 < 4; ++i2)
#pragma unroll
            for (int j = 0; j < 4; ++j) acc2[i2][j] = 0ull;

        const float* xp = xs + ty * 8;
        const float* ep = es + tx * 4;
#pragma unroll 4
        for (int d = 0; d < DD; ++d) {
            // 8 o-values as 4 aligned f32x2 pairs straight from smem.
            const ulonglong2 A0 = *reinterpret_cast<const ulonglong2*>(xp);
            const ulonglong2 A1 = *reinterpret_cast<const ulonglong2*>(xp + 4);
            const float4 bv = *reinterpret_cast<const float4*>(ep);
            uint64_t b2[4];
            PACK2(b2[0], bv.x); PACK2(b2[1], bv.y);
            PACK2(b2[2], bv.z); PACK2(b2[3], bv.w);
            const uint64_t a2[4] = {A0.x, A0.y, A1.x, A1.y};
#pragma unroll
            for (int i2 = 0; i2 < 4; ++i2)
#pragma unroll
                for (int j = 0; j < 4; ++j)
                    FMA2(acc2[i2][j], a2[i2], b2[j]);
            xp += BLOCK_O;
            ep += BLOCK_K;
        }

        // Running argmin update. Per-thread k strictly ascending so strict '<'
        // keeps the first (lowest) index on ties, matching argmin.
#pragma unroll
        for (int j = 0; j < 4; ++j) {
            const int k = kt + tx * 4 + j;
            const float e2 = g_e2[k];
#pragma unroll
            for (int i2 = 0; i2 < 4; ++i2) {
                const float slo = __uint_as_float((uint32_t)acc2[i2][j]);
                const float shi = __uint_as_float((uint32_t)(acc2[i2][j] >> 32));
                float vlo = fmaf(-2.f, slo, e2);
                float vhi = fmaf(-2.f, shi, e2);
                if (vlo < bestv[2 * i2])     { bestv[2 * i2] = vlo;     bestk[2 * i2] = k; }
                if (vhi < bestv[2 * i2 + 1]) { bestv[2 * i2 + 1] = vhi; bestk[2 * i2 + 1] = k; }
            }
        }
    }

    // Reduce across the 16 k-lanes (tx) sharing the same o rows.
#pragma unroll
    for (int i = 0; i < 8; ++i) {
        float v = bestv[i];
        int   kk = bestk[i];
#pragma unroll
        for (int off = 8; off >= 1; off >>= 1) {
            float ov = __shfl_xor_sync(0xFFFFFFFFu, v,  off);
            int   ok = __shfl_xor_sync(0xFFFFFFFFu, kk, off);
            if (ov < v || (ov == v && ok < kk)) { v = ov; kk = ok; }
        }
        if (tx == 0) {
            const int o = ty * 8 + i;
            ks[o] = kk;
            if (argout) argout[b * OO + o0 + o] = (float)kk;
        }
    }
    __syncthreads();

    // Gather quant[b,d,o] = emb[d, ks[o]]. Stores coalesced over o; loads hit
    // the L2-resident 1 MB codebook.
    if (quant) {
        float* qb = quant + (size_t)b * DD * OO + o0;
        for (int idx = tid; idx < DD * BLOCK_O; idx += NT) {
            int d = idx >> 7;
            int o = idx & (BLOCK_O - 1);
            qb[d * OO + o] = emb[d * KK + ks[o]];
        }
    }
}

// ---------------------------------------------------------------------------
extern "C" void kernel_launch(void* const* d_in, const int* in_sizes, int n_in,
                              void* d_out, int out_size) {
    const float* x   = (const float*)d_in[0];
    const float* emb = (const float*)d_in[1];
    float* out = (float*)d_out;

    const int QN = BB * DD * OO;   // quant elements
    const int AN = BB * OO;        // argmin elements

    float* quant  = nullptr;
    float* argout = nullptr;
    if (out_size >= QN) {
        quant = out;
        if (out_size >= QN + AN) argout = out + QN;
    } else if (out_size >= AN) {
        argout = out;   // argmin-only layout
    }

    const int smem_bytes = (DD * BLOCK_O + DD * BLOCK_K) * (int)sizeof(float); // 192 KB
    cudaFuncSetAttribute(vq_kernel, cudaFuncAttributeMaxDynamicSharedMemorySize, smem_bytes);

    e2_kernel<<<KK / 256, 256>>>(emb);

    dim3 grid(OO / BLOCK_O, BB);
    vq_kernel<<<grid, NT, smem_bytes>>>(x, emb, quant, argout);
}

// round 8
// speedup vs baseline: 1.7887x; 1.2521x over previous
#include <cuda_runtime.h>
#include <math_constants.h>
#include <cstdint>

#define BB 64
#define DD 256
#define OO 1024
#define KK 1024

#define OT  64               // o-tile per CTA
#define KT  128              // k-tile per outer iteration
#define NKT (KK / KT)        // 8
#define DC  32               // d per staged chunk
#define NDC (DD / DC)        // 8
#define NT  256              // 8 warps: 2 (o) x 4 (k)

// Padded smem strides (floats): conflict-free fragment LDS.
#define AS 72                // A rows: 64 o + 8 pad
#define BS 136               // B rows: 128 k + 8 pad

// smem layout in floats
#define AHI  0
#define ALO  (AHI + DC * AS)         // 2304
#define BHI  (ALO + DC * AS)         // 4608
#define BLO  (BHI + DC * BS)         // 8960
#define REDV (BLO + DC * BS)         // 13312: [4][64] float
#define REDK (REDV + 256)            // [4][64] int
#define KSO  (REDK + 256)            // [64] int
#define SM_FLOATS (KSO + 64)         // 13888
#define SM_BYTES  (SM_FLOATS * 4)    // 55552

// Scratch for ||e_k||^2.
__device__ float g_e2[KK];

// m16n8k8 tf32 MMA (legacy HMMA path, sm_80+ -> compiles on plain sm_100).
#define MMA(c, a, b)                                                          \
    asm volatile(                                                             \
        "mma.sync.aligned.m16n8k8.row.col.f32.tf32.tf32.f32 "                 \
        "{%0,%1,%2,%3}, {%4,%5,%6,%7}, {%8,%9}, {%0,%1,%2,%3};"               \
        : "+f"((c)[0]), "+f"((c)[1]), "+f"((c)[2]), "+f"((c)[3])              \
        : "r"((a)[0]), "r"((a)[1]), "r"((a)[2]), "r"((a)[3]),                 \
          "r"((b)[0]), "r"((b)[1]))

__device__ __forceinline__ void tf32_split(float v, float& hi, float& lo) {
    uint32_t h;
    asm("cvt.rna.tf32.f32 %0, %1;" : "=r"(h) : "f"(v));
    hi = __uint_as_float(h);
    float r = v - hi;
    uint32_t l;
    asm("cvt.rna.tf32.f32 %0, %1;" : "=r"(l) : "f"(r));
    lo = __uint_as_float(l);
}

// ---------------------------------------------------------------------------
__global__ void e2_kernel(const float* __restrict__ emb) {
    int k = blockIdx.x * blockDim.x + threadIdx.x;
    float s = 0.f;
#pragma unroll 8
    for (int d = 0; d < DD; ++d) {
        float v = emb[d * KK + k];
        s = fmaf(v, v, s);
    }
    g_e2[k] = s;
}

// ---------------------------------------------------------------------------
// Fused 3xTF32 mma.sync GEMM + running argmin + gather.
// CTA: one b x 64 o. Warp (wo,wk) computes o[wo*32..+32) x k[wk*32..+32)
// of each 64x128 k-tile. 3 passes: hi*hi + lo*hi + hi*lo (fp32 accum).
// ---------------------------------------------------------------------------
extern __shared__ float sm[];

__global__ __launch_bounds__(NT, 2)
void vq_tc(const float* __restrict__ x, const float* __restrict__ emb,
           float* __restrict__ quant, float* __restrict__ argout) {
    const int tid  = threadIdx.x;
    const int lane = tid & 31;
    const int wid  = tid >> 5;
    const int wo   = wid & 1;       // o half
    const int wk   = wid >> 1;      // k quarter
    const int b    = blockIdx.y;
    const int o0   = blockIdx.x * OT;
    const int l4   = lane & 3;
    const int lr   = lane >> 2;

    const float4* x4 = reinterpret_cast<const float4*>(x + (size_t)b * DD * OO);
    const float4* e4 = reinterpret_cast<const float4*>(emb);

    float bestv[4] = {CUDART_INF_F, CUDART_INF_F, CUDART_INF_F, CUDART_INF_F};
    int   bestk[4] = {0, 0, 0, 0};

    for (int kt = 0; kt < NKT; ++kt) {
        float c[2][4][4];
#pragma unroll
        for (int mt = 0; mt < 2; ++mt)
#pragma unroll
            for (int nt = 0; nt < 4; ++nt)
#pragma unroll
                for (int q = 0; q < 4; ++q) c[mt][nt][q] = 0.f;

        for (int dc = 0; dc < NDC; ++dc) {
            const int d0 = dc * DC;

            // ---- gmem loads first (max MLP), then split+store
            float4 xv[2], ev[4];
#pragma unroll
            for (int it = 0; it < 2; ++it) {
                int idx = tid + it * NT;            // 512 float4: 64o x 32d
                int d = idx >> 4, o4 = idx & 15;
                xv[it] = x4[(size_t)(d0 + d) * (OO / 4) + (o0 >> 2) + o4];
            }
#pragma unroll
            for (int it = 0; it < 4; ++it) {
                int idx = tid + it * NT;            // 1024 float4: 128k x 32d
                int d = idx >> 5, k4 = idx & 31;
                ev[it] = e4[(size_t)(d0 + d) * (KK / 4) + kt * (KT / 4) + k4];
            }
            __syncthreads();                        // prior mma reads done
#pragma unroll
            for (int it = 0; it < 2; ++it) {
                int idx = tid + it * NT;
                int d = idx >> 4, o4 = idx & 15;
                float h0, l0, h1, l1, h2, l2, h3, l3;
                tf32_split(xv[it].x, h0, l0); tf32_split(xv[it].y, h1, l1);
                tf32_split(xv[it].z, h2, l2); tf32_split(xv[it].w, h3, l3);
                *reinterpret_cast<float4*>(sm + AHI + d * AS + o4 * 4) = make_float4(h0, h1, h2, h3);
                *reinterpret_cast<float4*>(sm + ALO + d * AS + o4 * 4) = make_float4(l0, l1, l2, l3);
            }
#pragma unroll
            for (int it = 0; it < 4; ++it) {
                int idx = tid + it * NT;
                int d = idx >> 5, k4 = idx & 31;
                float h0, l0, h1, l1, h2, l2, h3, l3;
                tf32_split(ev[it].x, h0, l0); tf32_split(ev[it].y, h1, l1);
                tf32_split(ev[it].z, h2, l2); tf32_split(ev[it].w, h3, l3);
                *reinterpret_cast<float4*>(sm + BHI + d * BS + k4 * 4) = make_float4(h0, h1, h2, h3);
                *reinterpret_cast<float4*>(sm + BLO + d * BS + k4 * 4) = make_float4(l0, l1, l2, l3);
            }
            __syncthreads();

            // ---- 4 k-steps of 8 d each
#pragma unroll
            for (int s8 = 0; s8 < 4; ++s8) {
                const int dd = s8 * 8 + l4;
                uint32_t ah[2][4], al[2][4];
#pragma unroll
                for (int mt = 0; mt < 2; ++mt) {
                    const int o = wo * 32 + mt * 16 + lr;
                    ah[mt][0] = __float_as_uint(sm[AHI + dd * AS + o]);
                    ah[mt][1] = __float_as_uint(sm[AHI + dd * AS + o + 8]);
                    ah[mt][2] = __float_as_uint(sm[AHI + (dd + 4) * AS + o]);
                    ah[mt][3] = __float_as_uint(sm[AHI + (dd + 4) * AS + o + 8]);
                    al[mt][0] = __float_as_uint(sm[ALO + dd * AS + o]);
                    al[mt][1] = __float_as_uint(sm[ALO + dd * AS + o + 8]);
                    al[mt][2] = __float_as_uint(sm[ALO + (dd + 4) * AS + o]);
                    al[mt][3] = __float_as_uint(sm[ALO + (dd + 4) * AS + o + 8]);
                }
                uint32_t bh[4][2], bl[4][2];
#pragma unroll
                for (int nt = 0; nt < 4; ++nt) {
                    const int n = wk * 32 + nt * 8 + lr;
                    bh[nt][0] = __float_as_uint(sm[BHI + dd * BS + n]);
                    bh[nt][1] = __float_as_uint(sm[BHI + (dd + 4) * BS + n]);
                    bl[nt][0] = __float_as_uint(sm[BLO + dd * BS + n]);
                    bl[nt][1] = __float_as_uint(sm[BLO + (dd + 4) * BS + n]);
                }
#pragma unroll
                for (int mt = 0; mt < 2; ++mt)
#pragma unroll
                    for (int nt = 0; nt < 4; ++nt) {
                        MMA(c[mt][nt], ah[mt], bh[nt]);   // hi*hi
                        MMA(c[mt][nt], al[mt], bh[nt]);   // lo*hi
                        MMA(c[mt][nt], ah[mt], bl[nt]);   // hi*lo
                    }
            }
        }

        // ---- running argmin over this k-tile (k strictly ascending per thread)
#pragma unroll
        for (int nt = 0; nt < 4; ++nt)
#pragma unroll
            for (int q = 0; q < 2; ++q) {
                const int k = kt * KT + wk * 32 + nt * 8 + 2 * l4 + q;
                const float e2v = __ldg(&g_e2[k]);
#pragma unroll
                for (int mt = 0; mt < 2; ++mt) {
                    float v0 = fmaf(-2.f, c[mt][nt][q], e2v);       // row lr
                    if (v0 < bestv[mt * 2])     { bestv[mt * 2] = v0;     bestk[mt * 2] = k; }
                    float v1 = fmaf(-2.f, c[mt][nt][2 + q], e2v);   // row lr+8
                    if (v1 < bestv[mt * 2 + 1]) { bestv[mt * 2 + 1] = v1; bestk[mt * 2 + 1] = k; }
                }
            }
    }

    // ---- reduce across the 4 lanes of each quad (same o rows, different k)
#pragma unroll
    for (int i = 0; i < 4; ++i) {
        float v = bestv[i];
        int   k = bestk[i];
#pragma unroll
        for (int off = 1; off <= 2; off <<= 1) {
            float ov = __shfl_xor_sync(0xFFFFFFFFu, v, off);
            int   ok = __shfl_xor_sync(0xFFFFFFFFu, k, off);
            if (ov < v || (ov == v && ok < k)) { v = ov; k = ok; }
        }
        if (l4 == 0) {
            const int o = wo * 32 + (i >> 1) * 16 + (i & 1) * 8 + lr;
            sm[REDV + wk * OT + o] = v;
            reinterpret_cast<int*>(sm + REDK)[wk * OT + o] = k;
        }
    }
    __syncthreads();

    // ---- combine 4 k-warps (wk ascending = k ascending: strict < keeps first)
    int* ksarr = reinterpret_cast<int*>(sm + KSO);
    if (tid < OT) {
        float v = sm[REDV + tid];
        int   k = reinterpret_cast<int*>(sm + REDK)[tid];
#pragma unroll
        for (int w = 1; w < 4; ++w) {
            float ov = sm[REDV + w * OT + tid];
            int   ok = reinterpret_cast<int*>(sm + REDK)[w * OT + tid];
            if (ov < v) { v = ov; k = ok; }
        }
        ksarr[tid] = k;
        if (argout) argout[b * OO + o0 + tid] = (float)k;
    }
    __syncthreads();

    // ---- gather quant[b,d,o] = emb[d, ks[o]]
    if (quant) {
        float* qb = quant + (size_t)b * DD * OO + o0;
        for (int idx = tid; idx < DD * OT; idx += NT) {
            int d = idx >> 6;
            int o = idx & (OT - 1);
            qb[d * OO + o] = emb[d * KK + ksarr[o]];
        }
    }
}

// ---------------------------------------------------------------------------
extern "C" void kernel_launch(void* const* d_in, const int* in_sizes, int n_in,
                              void* d_out, int out_size) {
    const float* x   = (const float*)d_in[0];
    const float* emb = (const float*)d_in[1];
    float* out = (float*)d_out;

    const int QN = BB * DD * OO;
    const int AN = BB * OO;

    float* quant  = nullptr;
    float* argout = nullptr;
    if (out_size >= QN) {
        quant = out;
        if (out_size >= QN + AN) argout = out + QN;
    } else if (out_size >= AN) {
        argout = out;
    }

    cudaFuncSetAttribute(vq_tc, cudaFuncAttributeMaxDynamicSharedMemorySize, SM_BYTES);

    e2_kernel<<<KK / 256, 256>>>(emb);

    dim3 grid(OO / OT, BB);
    vq_tc<<<grid, NT, SM_BYTES>>>(x, emb, quant, argout);
}